// round 5
// baseline (speedup 1.0000x reference)
#include <cuda_runtime.h>
#include <math.h>
#include <stdint.h>

#define NUM_C   100
#define CPAD    128
#define DIM     256
#define DIM4    64          // DIM/4
#define TEMPV   0.7f
#define EPSV    1e-8f
#define RPB     64          // rows per block in main kernel

// ---------------- device scratch (no allocation allowed) ----------------
__device__ float g_sum[CPAD * DIM];     // class sums
__device__ float g_cnt[CPAD];           // class counts (float)
__device__ float g_protoT[CPAD * DIM];  // proto / (||proto|| * T)
__device__ float g_countf[CPAD];
__device__ int   g_is64;

// ---------------- K0: zero scratch + detect label dtype ----------------
// If labels are int64 (values in [0,100)), every odd 32-bit word is 0.
// If int32, the odd words are labels[1,3,...] — all-zero has ~0 probability.
__global__ void k_init(const int* lab32, int n, float* out) {
    int b = blockIdx.x, t = threadIdx.x;
    if (b == 0) {
        __shared__ int sflag[256];
        int f = 0;
        int half = n >> 1;   // probes: odd words among first n int32s (safe for both dtypes)
        for (int i = t; i < half; i += 256) f |= lab32[2 * i + 1];
        sflag[t] = f;
        __syncthreads();
        for (int s = 128; s > 0; s >>= 1) {
            if (t < s) sflag[t] |= sflag[t + s];
            __syncthreads();
        }
        if (t == 0) g_is64 = (sflag[0] == 0) ? 1 : 0;
    } else {
        int idx = (b - 1) * 1024 + t * 4;   // 32 blocks * 1024 floats = 32768 = CPAD*DIM
        float4 z = make_float4(0.f, 0.f, 0.f, 0.f);
        *(float4*)&g_sum[idx] = z;
        if (b == 1) {
            if (t < CPAD) g_cnt[t] = 0.f;
            if (t == 0) out[0] = 0.f;
        }
    }
}

__device__ __forceinline__ int get_label(const void* lab, int i, int is64) {
    return is64 ? (int)((const long long*)lab)[i] : ((const int*)lab)[i];
}

// ---------------- K1: scatter-add class sums + counts ----------------
__global__ void k_scatter(const float* __restrict__ f, const void* __restrict__ lab, int n) {
    int tid = blockIdx.x * blockDim.x + threadIdx.x;
    if (tid >= n * DIM4) return;
    int row = tid >> 6;          // tid / 64
    int q   = tid & 63;
    int is64 = g_is64;
    int c = get_label(lab, row, is64);
    float4 v = ((const float4*)f)[(size_t)row * DIM4 + q];
    float* dst = &g_sum[c * DIM + q * 4];
    atomicAdd(dst + 0, v.x);
    atomicAdd(dst + 1, v.y);
    atomicAdd(dst + 2, v.z);
    atomicAdd(dst + 3, v.w);
    if (q == 0) atomicAdd(&g_cnt[c], 1.0f);
}

// ---------------- K2: finalize prototypes: protoT = proto/(||proto||*T) ----------------
__global__ void k_proto() {
    int c = blockIdx.x, t = threadIdx.x;       // CPAD blocks x 256 threads
    float cnt = g_cnt[c];
    float p = g_sum[c * DIM + t] / fmaxf(cnt, 1.0f);
    __shared__ float red[256];
    red[t] = p * p;
    __syncthreads();
    for (int s = 128; s > 0; s >>= 1) {
        if (t < s) red[t] += red[t + s];
        __syncthreads();
    }
    float nrm = fmaxf(sqrtf(red[0]), EPSV);
    g_protoT[c * DIM + t] = p / (nrm * TEMPV);
    if (t == 0) g_countf[c] = cnt;
}

// ---------------- K3: main kernel ----------------
// For each row i: dot_ic = f_i . protoT_c ; val = dot_ic / max(||f_i||,eps) = sim_ic/T
// row_sum = sum_c count_c * exp(val) ; loss_i = log(row_sum) - val_{label_i}
// Smem: prot4[CPAD][65] f4 + frow4[RPB][65] f4 (stride 65 kills bank conflicts) + tails.
__global__ void __launch_bounds__(256, 1)
k_main(const float* __restrict__ f, const void* __restrict__ lab, float* out, int n) {
    extern __shared__ float4 sm4[];
    float4* prot4 = sm4;                         // CPAD * 65
    float4* frow4 = sm4 + CPAD * 65;             // RPB  * 65
    float*  tail  = (float*)(sm4 + (CPAD + RPB) * 65);
    float*  countf_sh = tail;                    // 128
    float*  invfn     = tail + 128;              // 64
    int*    lab_sh    = (int*)(tail + 192);      // 64
    float*  red       = tail + 256;              // 16

    int t = threadIdx.x;
    int row0 = blockIdx.x * RPB;
    int is64 = g_is64;

    // load protoT tile (all classes)
    const float4* gp = (const float4*)g_protoT;
    for (int idx = t; idx < CPAD * DIM4; idx += 256) {
        int c = idx >> 6, kk = idx & 63;
        prot4[c * 65 + kk] = gp[idx];
    }
    // load 64 feature rows
    const float4* gf = (const float4*)f;
    for (int idx = t; idx < RPB * DIM4; idx += 256) {
        int r = idx >> 6, kk = idx & 63;
        frow4[r * 65 + kk] = gf[(size_t)(row0 + r) * DIM4 + kk];
    }
    if (t < CPAD) countf_sh[t] = g_countf[t];
    if (t < RPB)  lab_sh[t] = get_label(lab, row0 + t, is64);
    __syncthreads();

    // per-row inverse norms (4 threads per row)
    {
        int r = t >> 2, p = t & 3;
        const float* fr = (const float*)&frow4[r * 65];
        float ss = 0.f;
        #pragma unroll 16
        for (int d = p * 64; d < p * 64 + 64; d++) ss += fr[d] * fr[d];
        ss += __shfl_xor_sync(0xffffffffu, ss, 1);
        ss += __shfl_xor_sync(0xffffffffu, ss, 2);
        if (p == 0) invfn[r] = 1.0f / fmaxf(sqrtf(ss), EPSV);
    }
    __syncthreads();

    // register-tiled dots: thread (tr,tc) owns rows tr*4..+3, classes {c8*16+tc}
    int tr = t >> 4, tc = t & 15;
    float acc[4][8];
    #pragma unroll
    for (int r = 0; r < 4; r++)
        #pragma unroll
        for (int c8 = 0; c8 < 8; c8++) acc[r][c8] = 0.f;

    const float4* ap = frow4 + (tr * 4) * 65;
    const float4* bp = prot4 + tc * 65;

    for (int kk = 0; kk < DIM4; kk++) {
        float4 a[4];
        #pragma unroll
        for (int r = 0; r < 4; r++) a[r] = ap[r * 65 + kk];
        #pragma unroll
        for (int c8 = 0; c8 < 8; c8++) {
            float4 b = bp[c8 * (16 * 65) + kk];
            #pragma unroll
            for (int r = 0; r < 4; r++) {
                acc[r][c8] = fmaf(a[r].x, b.x,
                             fmaf(a[r].y, b.y,
                             fmaf(a[r].z, b.z,
                             fmaf(a[r].w, b.w, acc[r][c8]))));
            }
        }
    }

    // epilogue: weighted exp-sum + diag, reduce across the 16 tc lanes
    float loss = 0.f;
    #pragma unroll
    for (int r = 0; r < 4; r++) {
        int row = tr * 4 + r;
        float ifn = invfn[row];
        int lb = lab_sh[row];
        float rowsum = 0.f, diag = 0.f;
        #pragma unroll
        for (int c8 = 0; c8 < 8; c8++) {
            int cls = c8 * 16 + tc;
            float val = acc[r][c8] * ifn;          // sim/T
            rowsum += countf_sh[cls] * expf(val);
            if (cls == lb) diag = val;
        }
        #pragma unroll
        for (int off = 8; off > 0; off >>= 1) {
            rowsum += __shfl_down_sync(0xffffffffu, rowsum, off, 16);
            diag   += __shfl_down_sync(0xffffffffu, diag,   off, 16);
        }
        if (tc == 0) loss += logf(rowsum) - diag;
    }
    if (tc == 0) red[tr] = loss;
    __syncthreads();
    if (t == 0) {
        float s = 0.f;
        #pragma unroll
        for (int i = 0; i < 16; i++) s += red[i];
        atomicAdd(out, s / (float)n);
    }
}

// ---------------- launch ----------------
extern "C" void kernel_launch(void* const* d_in, const int* in_sizes, int n_in,
                              void* d_out, int out_size) {
    const float* f = (const float*)d_in[0];
    const void*  lab = d_in[1];
    float* out = (float*)d_out;
    int n = in_sizes[1];                 // 8192

    int smem = (CPAD + RPB) * 65 * 16 + 272 * 4;   // 200768 B
    cudaFuncSetAttribute(k_main, cudaFuncAttributeMaxDynamicSharedMemorySize, smem);

    k_init<<<33, 256>>>((const int*)lab, n, out);
    k_scatter<<<(n * DIM4 + 255) / 256, 256>>>(f, lab, n);
    k_proto<<<CPAD, 256>>>();
    k_main<<<n / RPB, 256, smem>>>(f, lab, out, n);
}

// round 7
// speedup vs baseline: 1.3782x; 1.3782x over previous
#include <cuda_runtime.h>
#include <cuda_bf16.h>
#include <math.h>
#include <stdint.h>

#define NUM_C   100
#define CPAD    128
#define DIM     256
#define DIM4    64
#define TEMPV   0.7f
#define EPSV    1e-8f
#define NROWS   8192

// B smem: padded row stride 264 bf16 = 528 bytes (132 words -> banks 4n+t, conflict-free)
#define BSTRIDE 528
#define BH_SIZE (128 * BSTRIDE)      // 67584
#define SMEM_DYN (2 * BH_SIZE)       // 135168

// ---------------- device scratch ----------------
__device__ float g_sum[CPAD * DIM];
__device__ float g_cnt[CPAD];
__device__ float g_countf[CPAD];
__device__ __align__(16) __nv_bfloat16 g_pTh[CPAD * DIM];  // protoT hi
__device__ __align__(16) __nv_bfloat16 g_pTl[CPAD * DIM];  // protoT lo
__device__ float g_ss2[NROWS * 2];                          // per-row |f|^2 halves
__device__ int   g_is64;

// ---------------- helpers ----------------
__device__ __forceinline__ uint32_t smem_u32(const void* p) {
    uint32_t a;
    asm("{ .reg .u64 t; cvta.to.shared.u64 t, %1; cvt.u32.u64 %0, t; }" : "=r"(a) : "l"(p));
    return a;
}
__device__ __forceinline__ int get_label(const void* lab, int i, int is64) {
    return is64 ? (int)((const long long*)lab)[i] : ((const int*)lab)[i];
}
// split a float2 into packed bf16x2 hi + bf16x2 lo (residual)
__device__ __forceinline__ void split2(float2 v, uint32_t& h, uint32_t& l) {
    __nv_bfloat16 hx = __float2bfloat16(v.x), hy = __float2bfloat16(v.y);
    float rx = v.x - __bfloat162float(hx);
    float ry = v.y - __bfloat162float(hy);
    __nv_bfloat162 H, L;
    H.x = hx; H.y = hy;
    L.x = __float2bfloat16(rx); L.y = __float2bfloat16(ry);
    h = *(uint32_t*)&H;
    l = *(uint32_t*)&L;
}
__device__ __forceinline__ void mma_bf16(float* d, const uint32_t* a, const uint32_t* b) {
    asm volatile(
        "mma.sync.aligned.m16n8k16.row.col.f32.bf16.bf16.f32 "
        "{%0,%1,%2,%3}, {%4,%5,%6,%7}, {%8,%9}, {%0,%1,%2,%3};"
        : "+f"(d[0]), "+f"(d[1]), "+f"(d[2]), "+f"(d[3])
        : "r"(a[0]), "r"(a[1]), "r"(a[2]), "r"(a[3]), "r"(b[0]), "r"(b[1]));
}
#define LDSM4(r, a) \
    asm volatile("ldmatrix.sync.aligned.m8n8.x4.shared.b16 {%0,%1,%2,%3}, [%4];" \
        : "=r"((r)[0]), "=r"((r)[1]), "=r"((r)[2]), "=r"((r)[3]) : "r"(a))

// ---------------- K0: zero scratch + detect label dtype ----------------
__global__ void k_init(const int* lab32, int n, float* out) {
    int b = blockIdx.x, t = threadIdx.x;
    if (b == 0) {
        __shared__ int sflag[256];
        int fl = 0;
        int half = n >> 1;
        for (int i = t; i < half; i += 256) fl |= lab32[2 * i + 1];
        sflag[t] = fl;
        __syncthreads();
        for (int s = 128; s > 0; s >>= 1) { if (t < s) sflag[t] |= sflag[t + s]; __syncthreads(); }
        if (t == 0) g_is64 = (sflag[0] == 0) ? 1 : 0;
    } else {
        int idx = (b - 1) * 1024 + t * 4;
        *(float4*)&g_sum[idx] = make_float4(0.f, 0.f, 0.f, 0.f);
        if (b == 1) {
            if (t < CPAD) g_cnt[t] = 0.f;
            if (t == 0) out[0] = 0.f;
        }
    }
}

// ---------------- K1: scatter-add sums/counts + per-row |f|^2 ----------------
__global__ void k_scatter(const float* __restrict__ f, const void* __restrict__ lab, int n) {
    int tid = blockIdx.x * blockDim.x + threadIdx.x;
    if (tid >= n * DIM4) return;
    int row = tid >> 6;
    int q   = tid & 63;
    int c = get_label(lab, row, g_is64);
    float4 v = ((const float4*)f)[(size_t)row * DIM4 + q];
    float* dst = &g_sum[c * DIM + q * 4];
    atomicAdd(dst + 0, v.x);
    atomicAdd(dst + 1, v.y);
    atomicAdd(dst + 2, v.z);
    atomicAdd(dst + 3, v.w);
    if (q == 0) atomicAdd(&g_cnt[c], 1.0f);
    float ss = v.x * v.x + v.y * v.y + v.z * v.z + v.w * v.w;
    #pragma unroll
    for (int off = 16; off > 0; off >>= 1) ss += __shfl_xor_sync(0xffffffffu, ss, off);
    if ((threadIdx.x & 31) == 0) g_ss2[row * 2 + ((q >> 5) & 1)] = ss;
}

// ---------------- K2: protoT = proto/(|proto|*T), split to bf16 hi/lo ----------------
__global__ void k_proto() {
    int c = blockIdx.x, t = threadIdx.x;
    float cnt = g_cnt[c];
    float p = g_sum[c * DIM + t] / fmaxf(cnt, 1.0f);
    __shared__ float red[256];
    red[t] = p * p;
    __syncthreads();
    for (int s = 128; s > 0; s >>= 1) { if (t < s) red[t] += red[t + s]; __syncthreads(); }
    float nrm = fmaxf(sqrtf(red[0]), EPSV);
    float v = p / (nrm * TEMPV);
    __nv_bfloat16 hi = __float2bfloat16(v);
    __nv_bfloat16 lo = __float2bfloat16(v - __bfloat162float(hi));
    g_pTh[c * DIM + t] = hi;
    g_pTl[c * DIM + t] = lo;
    if (t == 0) g_countf[c] = cnt;
}

// ---------------- K3: HMMA bf16x3 GEMM + fused contrastive epilogue ----------------
// 128 CTAs x 128 threads. Warp w owns rows [blk*64 + w*16, +16), all 128 classes.
// acc[nt][4]: nt-th 8-class tile; d0,d1 = row g cols {2t,2t+1}; d2,d3 = row g+8.
__global__ void __launch_bounds__(128, 1)
k_main(const float* __restrict__ f, const void* __restrict__ lab, float* out, int n) {
    extern __shared__ char dsm[];               // [Bh: 67584][Bl: 67584]
    __shared__ float cnt_sh[CPAD];
    __shared__ float invfn_sh[64];
    __shared__ int   lab_sh[64];
    __shared__ float red_sh[4];

    int t = threadIdx.x, wid = t >> 5, lid = t & 31;
    int g = lid >> 2, tq = lid & 3;
    int row0 = blockIdx.x * 64;

    // fill protoT hi/lo smem (padded stride)
    const uint4* gh = (const uint4*)g_pTh;
    const uint4* gl = (const uint4*)g_pTl;
    for (int idx = t; idx < 128 * 32; idx += 128) {
        int r = idx >> 5, c = idx & 31;
        *(uint4*)(dsm + r * BSTRIDE + c * 16) = gh[idx];
        *(uint4*)(dsm + BH_SIZE + r * BSTRIDE + c * 16) = gl[idx];
    }
    if (t < CPAD) cnt_sh[t] = g_countf[t];
    if (t < 64) {
        float2 s2 = ((const float2*)g_ss2)[row0 + t];
        invfn_sh[t] = 1.0f / fmaxf(sqrtf(s2.x + s2.y), EPSV);
        lab_sh[t] = get_label(lab, row0 + t, g_is64);
    }
    __syncthreads();

    uint32_t Bh_u = smem_u32(dsm);
    uint32_t Bl_u = Bh_u + BH_SIZE;
    // ldmatrix.x4 lane address: matrix m = lid>>3 -> (n-half m>>1, k-half m&1)
    int m8 = lid >> 3, j8 = lid & 7;
    uint32_t laneoff = (uint32_t)(((m8 >> 1) * 8 + j8) * BSTRIDE + (m8 & 1) * 16);

    int wr0 = wid * 16 + g;                     // row-in-block (g); g+8 is +8
    const float* fr0 = f + (size_t)(row0 + wr0) * DIM;
    const float* fr1 = fr0 + 8 * DIM;

    float acc[16][4];
    #pragma unroll
    for (int i = 0; i < 16; i++) { acc[i][0] = acc[i][1] = acc[i][2] = acc[i][3] = 0.f; }

    #pragma unroll 4
    for (int kt = 0; kt < 16; kt++) {
        int k0 = kt * 16 + 2 * tq;
        uint32_t ah[4], al[4];
        split2(*(const float2*)(fr0 + k0),     ah[0], al[0]);   // rows 0-7, k 0-7
        split2(*(const float2*)(fr1 + k0),     ah[1], al[1]);   // rows 8-15, k 0-7
        split2(*(const float2*)(fr0 + k0 + 8), ah[2], al[2]);   // rows 0-7, k 8-15
        split2(*(const float2*)(fr1 + k0 + 8), ah[3], al[3]);   // rows 8-15, k 8-15
        uint32_t kb = (uint32_t)(kt * 32) + laneoff;
        #pragma unroll
        for (int ntp = 0; ntp < 8; ntp++) {
            uint32_t bh[4], bl[4];
            LDSM4(bh, Bh_u + (uint32_t)(ntp * 16 * BSTRIDE) + kb);
            LDSM4(bl, Bl_u + (uint32_t)(ntp * 16 * BSTRIDE) + kb);
            mma_bf16(acc[2 * ntp],     ah, bh);
            mma_bf16(acc[2 * ntp + 1], ah, bh + 2);
            mma_bf16(acc[2 * ntp],     al, bh);
            mma_bf16(acc[2 * ntp + 1], al, bh + 2);
            mma_bf16(acc[2 * ntp],     ah, bl);
            mma_bf16(acc[2 * ntp + 1], ah, bl + 2);
        }
    }

    // ---- epilogue: rows wr0 and wr0+8, 32 classes per thread each ----
    float ifn0 = invfn_sh[wr0],     ifn1 = invfn_sh[wr0 + 8];
    int   lb0  = lab_sh[wr0],       lb1  = lab_sh[wr0 + 8];
    float rs0 = 0.f, rs1 = 0.f, dg0 = 0.f, dg1 = 0.f;
    #pragma unroll
    for (int nt = 0; nt < 16; nt++) {
        #pragma unroll
        for (int cc = 0; cc < 2; cc++) {
            int cls = nt * 8 + 2 * tq + cc;
            float cw = cnt_sh[cls];
            float v0 = acc[nt][cc]     * ifn0;
            float v1 = acc[nt][2 + cc] * ifn1;
            rs0 += cw * __expf(v0);
            rs1 += cw * __expf(v1);
            if (cls == lb0) dg0 = v0;
            if (cls == lb1) dg1 = v1;
        }
    }
    #pragma unroll
    for (int o = 1; o <= 2; o <<= 1) {
        rs0 += __shfl_xor_sync(0xffffffffu, rs0, o);
        rs1 += __shfl_xor_sync(0xffffffffu, rs1, o);
        dg0 += __shfl_xor_sync(0xffffffffu, dg0, o);
        dg1 += __shfl_xor_sync(0xffffffffu, dg1, o);
    }
    float lv = (tq == 0) ? (logf(rs0) - dg0 + logf(rs1) - dg1) : 0.f;
    #pragma unroll
    for (int o = 16; o > 0; o >>= 1) lv += __shfl_down_sync(0xffffffffu, lv, o);
    if (lid == 0) red_sh[wid] = lv;
    __syncthreads();
    if (t == 0)
        atomicAdd(out, (red_sh[0] + red_sh[1] + red_sh[2] + red_sh[3]) / (float)n);
}

// ---------------- launch ----------------
extern "C" void kernel_launch(void* const* d_in, const int* in_sizes, int n_in,
                              void* d_out, int out_size) {
    const float* f = (const float*)d_in[0];
    const void*  lab = d_in[1];
    float* out = (float*)d_out;
    int n = in_sizes[1];   // 8192

    cudaFuncSetAttribute(k_main, cudaFuncAttributeMaxDynamicSharedMemorySize, SMEM_DYN);

    k_init<<<33, 256>>>((const int*)lab, n, out);
    k_scatter<<<(n * DIM4 + 255) / 256, 256>>>(f, lab, n);
    k_proto<<<CPAD, 256>>>();
    k_main<<<n / 64, 128, SMEM_DYN>>>(f, lab, out, n);
}